// round 16
// baseline (speedup 1.0000x reference)
#include <cuda_runtime.h>
#include <cuda_fp16.h>
#include <math.h>
#include <stdint.h>

#define B 4
#define S 2048
#define E 512
#define H 8
#define D 64
#define FF 2048
#define NTOK (B*S)

// ---- device scratch (static, allocation-free) ----
__device__ __half g_Vt[(size_t)B * H * D * S];   // V transposed: [b][h][d][s]
__device__ float  g_Q[(size_t)B * H * S];        // [b,h,s]
__device__ float  g_K[(size_t)B * H * S];        // [b,h,s]
__device__ __half g_HO[(size_t)NTOK * E];        // head_out [s][e]
__device__ __half g_MID[(size_t)NTOK * FF];      // GELU(h@W1+b1)
__device__ __half g_Wt1[(size_t)FF * E];         // W1^T [N=FF][K=E]
__device__ __half g_Wt2[(size_t)E * FF];         // W2^T [N=E][K=FF]

// ============================================================
// Helpers (arch-generic PTX: mma.sync / cp.async / ldmatrix / ex2.f16x2)
// ============================================================
__device__ __forceinline__ uint32_t smem_u32(const void* p) {
    uint32_t a;
    asm("{ .reg .u64 t; cvta.to.shared.u64 t, %1; cvt.u32.u64 %0, t; }" : "=r"(a) : "l"(p));
    return a;
}
#define CP_ASYNC16(dst, src) \
    asm volatile("cp.async.cg.shared.global [%0], [%1], 16;" :: "r"(dst), "l"(src) : "memory")
#define CP_COMMIT() asm volatile("cp.async.commit_group;" ::: "memory")
template<int N> __device__ __forceinline__ void cp_wait() {
    asm volatile("cp.async.wait_group %0;" :: "n"(N) : "memory");
}
// m16n8k16 fp16 mma, fp32 accum
__device__ __forceinline__ void mma_f16(float* c, const uint32_t* a, const uint32_t* b) {
    asm volatile(
        "mma.sync.aligned.m16n8k16.row.col.f32.f16.f16.f32 "
        "{%0,%1,%2,%3}, {%4,%5,%6,%7}, {%8,%9}, {%0,%1,%2,%3};"
        : "+f"(c[0]), "+f"(c[1]), "+f"(c[2]), "+f"(c[3])
        : "r"(a[0]), "r"(a[1]), "r"(a[2]), "r"(a[3]), "r"(b[0]), "r"(b[1]));
}
__device__ __forceinline__ void ldsm_x4(uint32_t* r, uint32_t addr) {
    asm volatile("ldmatrix.sync.aligned.m8n8.x4.shared.b16 {%0,%1,%2,%3}, [%4];"
        : "=r"(r[0]), "=r"(r[1]), "=r"(r[2]), "=r"(r[3]) : "r"(addr));
}
__device__ __forceinline__ uint32_t pack_h2(float lo, float hi) {
    __half2 h = __floats2half2_rn(lo, hi);
    return *reinterpret_cast<uint32_t*>(&h);
}
__device__ __forceinline__ __half2 u2h2(uint32_t u) {
    return *reinterpret_cast<__half2*>(&u);
}
__device__ __forceinline__ uint32_t h22u(__half2 h) {
    return *reinterpret_cast<uint32_t*>(&h);
}

// ============================================================
// Kernel 0: weight transpose + fp16 convert: W[K][N] -> Wt[N][K] (half)
// ============================================================
__global__ __launch_bounds__(256) void transpose_half_kernel(
    const float* __restrict__ W, __half* __restrict__ Wt, int K, int N)
{
    __shared__ float t[32][33];
    const int n0 = blockIdx.x * 32;
    const int k0 = blockIdx.y * 32;
    const int tx = threadIdx.x & 31;
    const int ty = threadIdx.x >> 5;
    #pragma unroll
    for (int r = 0; r < 4; r++)
        t[ty + r * 8][tx] = W[(size_t)(k0 + ty + r * 8) * N + n0 + tx];
    __syncthreads();
    #pragma unroll
    for (int r = 0; r < 4; r++)
        Wt[(size_t)(n0 + ty + r * 8) * K + k0 + tx] = __float2half_rn(t[tx][ty + r * 8]);
}

// ============================================================
// Kernel 1: LayerNorm + projections, 32 tokens per CTA (unchanged).
// ============================================================
#define LN_SMEM_BYTES (32 * 512 * 4)

__global__ __launch_bounds__(256) void ln_proj_kernel(
    const float* __restrict__ x,
    const float* __restrict__ Wv, const float* __restrict__ bv,
    const float* __restrict__ Wq, const float* __restrict__ bq,
    const float* __restrict__ Wk, const float* __restrict__ bk)
{
    extern __shared__ float smem[];
    float (*xn)[512] = (float(*)[512])smem;

    const int tb = blockIdx.x * 32;
    const int tid = threadIdx.x;
    const int lane = tid & 31, wid = tid >> 5;

    #pragma unroll
    for (int tt = 0; tt < 4; tt++) {
        const int t = wid * 4 + tt;
        const float* xin = x + (size_t)(tb + t) * E;
        float v[16];
        float s = 0.f, ss = 0.f;
        #pragma unroll
        for (int j = 0; j < 16; j++) {
            v[j] = xin[lane + j * 32];
            s += v[j];
            ss = fmaf(v[j], v[j], ss);
        }
        #pragma unroll
        for (int o = 16; o > 0; o >>= 1) {
            s  += __shfl_xor_sync(0xffffffffu, s, o);
            ss += __shfl_xor_sync(0xffffffffu, ss, o);
        }
        const float mean = s * (1.0f / E);
        const float var  = ss * (1.0f / E) - mean * mean;
        const float rstd = rsqrtf(var + 1e-5f);
        #pragma unroll
        for (int j = 0; j < 16; j++)
            xn[t][lane + j * 32] = (v[j] - mean) * rstd;
    }
    __syncthreads();

    const int bidx = tb >> 11;
    const int s0 = tb & (S - 1);

    #pragma unroll
    for (int rep = 0; rep < 2; rep++) {
        const int e = tid + rep * 256;
        const int h = e >> 6, d = e & 63;
        const float* w = Wv + (size_t)h * D * D + d;
        const float bvv = bv[e];
        float acc[32];
        #pragma unroll
        for (int t = 0; t < 32; t++) acc[t] = bvv;
        const float* xh = &xn[0][h * 64];
        #pragma unroll
        for (int i = 0; i < D; i += 4) {
            const float w0 = w[i * D];
            const float w1 = w[(i + 1) * D];
            const float w2 = w[(i + 2) * D];
            const float w3 = w[(i + 3) * D];
            #pragma unroll
            for (int t = 0; t < 32; t++) {
                const float4 xv = *(const float4*)&xh[t * 512 + i];
                float a0 = fmaf(xv.x, w0, acc[t]);
                float a1 = fmaf(xv.y, w1, a0);
                float a2 = fmaf(xv.z, w2, a1);
                acc[t] = fmaf(xv.w, w3, a2);
            }
        }
        uint32_t hb[16];
        #pragma unroll
        for (int t = 0; t < 16; t++) hb[t] = pack_h2(acc[t * 2], acc[t * 2 + 1]);
        uint4* dst = (uint4*)(g_Vt + ((size_t)(bidx * H + h) * D + d) * S + s0);
        const uint4* srcv = (const uint4*)hb;
        #pragma unroll
        for (int i = 0; i < 4; i++) dst[i] = srcv[i];
    }

    {
        const int t = tid >> 3, h = tid & 7;
        const float* wq = Wq + h * D;
        const float* wk = Wk + h * D;
        const float* xh = xn[t] + h * 64;
        float accq = bq[h], acck = bk[h];
        #pragma unroll
        for (int i = 0; i < D; i++) {
            const float xv = xh[i];
            accq = fmaf(xv, wq[i], accq);
            acck = fmaf(xv, wk[i], acck);
        }
        g_Q[((size_t)bidx * H + h) * S + s0 + t] = accq;
        g_K[((size_t)bidx * H + h) * S + s0 + t] = acck;
    }
}

// ============================================================
// Kernel 2: attention — R15 winner, with __launch_bounds__(128, 8)
// to cap regs at 64 and raise occupancy (8 CTAs/SM).
// smem: KK 8KB | 2 x 8KB V buffers
// ============================================================
#define ATT_SMEM_BYTES (8192 + 2 * 8192)

__global__ __launch_bounds__(128, 8) void attn_kernel()
{
    extern __shared__ float smem[];
    uint2* KK = (uint2*)smem;                // 1024 pairs
    const uint32_t sbase = smem_u32(smem);
    const uint32_t vtbuf = sbase + 8192;

    const int bh = blockIdx.y;
    const int q0 = blockIdx.x * 64;
    const int tid = threadIdx.x;
    const int lane = tid & 31, wid = tid >> 5;
    const int l7 = lane & 7;
    const int cl = lane & 3;

    const float CB = -0.1803368801111204f;   // -log2e/8
    const float CQ =  0.3606737602222409f;   // log2e/4
    for (int j = tid; j < S / 2; j += 128) {
        const float2 kv = *(const float2*)&g_K[(size_t)bh * S + 2 * j];
        uint2 e;
        e.x = pack_h2(kv.x, kv.y);
        e.y = pack_h2(kv.x * kv.x * CB, kv.y * kv.y * CB);
        KK[j] = e;
    }

    const int r0 = wid * 16 + (lane >> 2);   // 0..63
    const float qc0 = g_Q[(size_t)bh * S + q0 + r0] * CQ;
    const float qc1 = g_Q[(size_t)bh * S + q0 + r0 + 8] * CQ;
    const __half2 qc0h = __floats2half2_rn(qc0, qc0);
    const __half2 qc1h = __floats2half2_rn(qc1, qc1);

    const __half* Vg = g_Vt + (size_t)bh * D * S;   // [d][s]
    auto loadV = [&](int kc, int buf) {
        #pragma unroll
        for (int p = 0; p < 4; p++) {
            const int row = (tid >> 3) + p * 16;
            const int seg = tid & 7;
            const __half* src = Vg + (size_t)row * S + kc * 64 + seg * 8;
            const uint32_t dst = vtbuf + buf * 8192 +
                (uint32_t)(row * 128 + ((seg ^ (row & 7)) * 16));
            CP_ASYNC16(dst, src);
        }
    };

    uint32_t vRow[4];
    #pragma unroll
    for (int ntp = 0; ntp < 4; ntp++)
        vRow[ntp] = (uint32_t)((ntp * 16 + ((lane >> 4) & 1) * 8 + l7) * 128);
    const int selV = (lane >> 3) & 1;

    loadV(0, 0);
    CP_COMMIT();

    float acc[8][4];
    #pragma unroll
    for (int j = 0; j < 8; j++)
        #pragma unroll
        for (int l = 0; l < 4; l++) acc[j][l] = 0.f;
    float accd[4] = {0.f, 0.f, 0.f, 0.f};
    const uint32_t ones[2] = { 0x3C003C00u, 0x3C003C00u };

    const int NCH = S / 64;
    for (int kc = 0; kc < NCH; kc++) {
        const int buf = kc & 1;
        cp_wait<0>();
        __syncthreads();
        if (kc + 1 < NCH) { loadV(kc + 1, buf ^ 1); CP_COMMIT(); }

        const uint32_t vb = vtbuf + (uint32_t)(buf * 8192);
        #pragma unroll
        for (int ks = 0; ks < 4; ks++) {
            const int jb = kc * 32 + ks * 8;
            const uint2 e0 = KK[jb + cl];
            const uint2 e1 = KK[jb + cl + 4];
            uint32_t a[4];
            a[0] = h22u(h2exp2(__hfma2(qc0h, u2h2(e0.x), u2h2(e0.y))));
            a[1] = h22u(h2exp2(__hfma2(qc1h, u2h2(e0.x), u2h2(e0.y))));
            a[2] = h22u(h2exp2(__hfma2(qc0h, u2h2(e1.x), u2h2(e1.y))));
            a[3] = h22u(h2exp2(__hfma2(qc1h, u2h2(e1.x), u2h2(e1.y))));
            mma_f16(accd, a, ones);
            const uint32_t sw = (uint32_t)(((ks * 2 + selV) ^ l7) * 16);
            #pragma unroll
            for (int ntp = 0; ntp < 4; ntp++) {
                uint32_t bb[4];
                ldsm_x4(bb, vb + vRow[ntp] + sw);
                mma_f16(acc[ntp * 2],     a, bb);
                mma_f16(acc[ntp * 2 + 1], a, bb + 2);
            }
        }
    }

    const float inv0 = 1.0f / accd[0];
    const float inv1 = 1.0f / accd[2];

    const int b = bh >> 3, h = bh & 7;
    #pragma unroll
    for (int nt = 0; nt < 8; nt++) {
        const int col = nt * 8 + cl * 2;
        const size_t t0 = ((size_t)b * S + q0 + r0) * E + h * D + col;
        const size_t t1 = ((size_t)b * S + q0 + r0 + 8) * E + h * D + col;
        __half2 o0 = __floats2half2_rn(acc[nt][0] * inv0, acc[nt][1] * inv0);
        __half2 o1 = __floats2half2_rn(acc[nt][2] * inv1, acc[nt][3] * inv1);
        *(__half2*)&g_HO[t0] = o0;
        *(__half2*)&g_HO[t1] = o1;
    }
}

// ============================================================
// Kernel 3/4: fp16 mma GEMM — best-known config:
// 128x128 CTA tile, BK=64, 3-stage cp.async, 16B-XOR swizzle.
// ============================================================
#define GEMM_SMEM_BYTES (3 * 32768)

template<int MODE>
__global__ __launch_bounds__(256) void hgemm_kernel(
    const __half* __restrict__ Bt, const float* __restrict__ bias,
    const float* __restrict__ res, float* __restrict__ Cout,
    int N, int K)
{
    extern __shared__ float smem[];
    const __half* A = (MODE == 0) ? g_HO : g_MID;

    const int tid = threadIdx.x;
    const int lane = tid & 31, wid = tid >> 5;
    const int l7 = lane & 7;
    const int bm = blockIdx.y * 128;
    const int bn = blockIdx.x * 128;
    const int wm = wid >> 2;
    const int wn = wid & 3;
    const uint32_t sbase = smem_u32(smem);

    const int lr = tid >> 3;
    const int lg = tid & 7;

    auto load_tile = [&](int kc, int st) {
        #pragma unroll
        for (int p = 0; p < 4; p++) {
            const int r = lr + p * 32;
            const uint32_t dst = sbase + (uint32_t)(st * 32768 + r * 128 + ((lg ^ (r & 7)) * 16));
            CP_ASYNC16(dst, A + (size_t)(bm + r) * K + kc * 64 + lg * 8);
            CP_ASYNC16(dst + 16384u, Bt + (size_t)(bn + r) * K + kc * 64 + lg * 8);
        }
    };

    uint32_t aRow[4];
    #pragma unroll
    for (int mt = 0; mt < 4; mt++)
        aRow[mt] = (uint32_t)((wm * 64 + mt * 16 + ((lane >> 3) & 1) * 8 + l7) * 128);
    const int selA = (lane >> 4) & 1;
    uint32_t bRow[2];
    #pragma unroll
    for (int ntp = 0; ntp < 2; ntp++)
        bRow[ntp] = 16384u + (uint32_t)((wn * 32 + ntp * 16 + ((lane >> 4) & 1) * 8 + l7) * 128);
    const int selB = (lane >> 3) & 1;

    float acc[4][4][4];
    #pragma unroll
    for (int i = 0; i < 4; i++)
        #pragma unroll
        for (int j = 0; j < 4; j++)
            #pragma unroll
            for (int l = 0; l < 4; l++) acc[i][j][l] = 0.f;

    const int nc = K / 64;
    load_tile(0, 0); CP_COMMIT();
    load_tile(1, 1); CP_COMMIT();

    for (int kc = 0; kc < nc; kc++) {
        const int st = kc % 3;
        if (kc + 1 < nc) cp_wait<1>(); else cp_wait<0>();
        __syncthreads();
        if (kc + 2 < nc) { load_tile(kc + 2, (kc + 2) % 3); CP_COMMIT(); }

        const uint32_t stb = sbase + (uint32_t)(st * 32768);
        #pragma unroll
        for (int ks = 0; ks < 4; ks++) {
            const uint32_t swA = (uint32_t)(((ks * 2 + selA) ^ l7) * 16);
            const uint32_t swB = (uint32_t)(((ks * 2 + selB) ^ l7) * 16);
            uint32_t a[4][4], b01[4], b23[4];
            #pragma unroll
            for (int mt = 0; mt < 4; mt++) ldsm_x4(a[mt], stb + aRow[mt] + swA);
            ldsm_x4(b01, stb + bRow[0] + swB);
            ldsm_x4(b23, stb + bRow[1] + swB);
            #pragma unroll
            for (int mt = 0; mt < 4; mt++) {
                mma_f16(acc[mt][0], a[mt], b01);
                mma_f16(acc[mt][1], a[mt], b01 + 2);
                mma_f16(acc[mt][2], a[mt], b23);
                mma_f16(acc[mt][3], a[mt], b23 + 2);
            }
        }
    }

    #pragma unroll
    for (int mt = 0; mt < 4; mt++) {
        const int r0 = bm + wm * 64 + mt * 16 + (lane >> 2);
        #pragma unroll
        for (int nt = 0; nt < 4; nt++) {
            const int col = bn + wn * 32 + nt * 8 + (lane & 3) * 2;
            const float bz0 = bias[col], bz1 = bias[col + 1];
            float c0 = acc[mt][nt][0] + bz0;
            float c1 = acc[mt][nt][1] + bz1;
            float c2 = acc[mt][nt][2] + bz0;
            float c3 = acc[mt][nt][3] + bz1;
            const size_t g0 = (size_t)r0 * N + col;
            const size_t g1 = (size_t)(r0 + 8) * N + col;
            if (MODE == 0) {
                c0 = c0 * normcdff(c0);
                c1 = c1 * normcdff(c1);
                c2 = c2 * normcdff(c2);
                c3 = c3 * normcdff(c3);
                *(__half2*)&g_MID[g0] = __floats2half2_rn(c0, c1);
                *(__half2*)&g_MID[g1] = __floats2half2_rn(c2, c3);
            } else {
                const float2 ra = *(const float2*)&res[g0];
                const float2 rb = *(const float2*)&res[g1];
                float2 v0; v0.x = c0 + ra.x; v0.y = c1 + ra.y;
                float2 v1; v1.x = c2 + rb.x; v1.y = c3 + rb.y;
                *(float2*)&Cout[g0] = v0;
                *(float2*)&Cout[g1] = v1;
            }
        }
    }
}

// ============================================================
extern "C" void kernel_launch(void* const* d_in, const int* in_sizes, int n_in,
                              void* d_out, int out_size)
{
    const float* input1 = (const float*)d_in[0];
    const float* Wv = (const float*)d_in[1];
    const float* bv = (const float*)d_in[2];
    const float* Wq = (const float*)d_in[3];
    const float* bq = (const float*)d_in[4];
    const float* Wk = (const float*)d_in[5];
    const float* bk = (const float*)d_in[6];
    const float* W1 = (const float*)d_in[7];
    const float* b1 = (const float*)d_in[8];
    const float* W2 = (const float*)d_in[9];
    const float* b2 = (const float*)d_in[10];
    float* out = (float*)d_out;

    __half* s_Wt1; cudaGetSymbolAddress((void**)&s_Wt1, g_Wt1);
    __half* s_Wt2; cudaGetSymbolAddress((void**)&s_Wt2, g_Wt2);

    // one-time setup (first call happens OUTSIDE graph capture)
    static bool s_init = false;
    static cudaStream_t s_side;
    static cudaEvent_t s_fork, s_join;
    if (!s_init) {
        cudaStreamCreateWithFlags(&s_side, cudaStreamNonBlocking);
        cudaEventCreateWithFlags(&s_fork, cudaEventDisableTiming);
        cudaEventCreateWithFlags(&s_join, cudaEventDisableTiming);
        cudaFuncSetAttribute(ln_proj_kernel, cudaFuncAttributeMaxDynamicSharedMemorySize, LN_SMEM_BYTES);
        cudaFuncSetAttribute(attn_kernel, cudaFuncAttributeMaxDynamicSharedMemorySize, ATT_SMEM_BYTES);
        cudaFuncSetAttribute(hgemm_kernel<0>, cudaFuncAttributeMaxDynamicSharedMemorySize, GEMM_SMEM_BYTES);
        cudaFuncSetAttribute(hgemm_kernel<1>, cudaFuncAttributeMaxDynamicSharedMemorySize, GEMM_SMEM_BYTES);
        s_init = true;
    }

    // fork: weight transposes run on side stream, concurrent with ln/attn
    cudaEventRecord(s_fork, 0);
    cudaStreamWaitEvent(s_side, s_fork, 0);
    transpose_half_kernel<<<dim3(FF / 32, E / 32), 256, 0, s_side>>>(W1, s_Wt1, E, FF);
    transpose_half_kernel<<<dim3(E / 32, FF / 32), 256, 0, s_side>>>(W2, s_Wt2, FF, E);
    cudaEventRecord(s_join, s_side);

    ln_proj_kernel<<<NTOK / 32, 256, LN_SMEM_BYTES>>>(input1, Wv, bv, Wq, bq, Wk, bk);
    attn_kernel<<<dim3(S / 64, B * H), 128, ATT_SMEM_BYTES>>>();

    // join before gemm0 consumes Wt1
    cudaStreamWaitEvent(0, s_join, 0);
    hgemm_kernel<0><<<dim3(FF / 128, NTOK / 128), 256, GEMM_SMEM_BYTES>>>(s_Wt1, b1, nullptr, nullptr, FF, E);
    hgemm_kernel<1><<<dim3(E / 128, NTOK / 128), 256, GEMM_SMEM_BYTES>>>(s_Wt2, b2, input1, out, E, FF);
}

// round 17
// speedup vs baseline: 1.0031x; 1.0031x over previous
#include <cuda_runtime.h>
#include <cuda_fp16.h>
#include <math.h>
#include <stdint.h>

#define B 4
#define S 2048
#define E 512
#define H 8
#define D 64
#define FF 2048
#define NTOK (B*S)

// ---- device scratch (static, allocation-free) ----
__device__ __half g_Vt[(size_t)B * H * D * S];   // V transposed: [b][h][d][s]
__device__ float  g_Q[(size_t)B * H * S];        // [b,h,s]
__device__ float  g_K[(size_t)B * H * S];        // [b,h,s]
__device__ __half g_HO[(size_t)NTOK * E];        // head_out [s][e]
__device__ __half g_MID[(size_t)NTOK * FF];      // GELU(h@W1+b1)
__device__ __half g_Wt1[(size_t)FF * E];         // W1^T [N=FF][K=E]
__device__ __half g_Wt2[(size_t)E * FF];         // W2^T [N=E][K=FF]

// ============================================================
// Helpers (arch-generic PTX: mma.sync / cp.async / ldmatrix / ex2.f16x2)
// ============================================================
__device__ __forceinline__ uint32_t smem_u32(const void* p) {
    uint32_t a;
    asm("{ .reg .u64 t; cvta.to.shared.u64 t, %1; cvt.u32.u64 %0, t; }" : "=r"(a) : "l"(p));
    return a;
}
#define CP_ASYNC16(dst, src) \
    asm volatile("cp.async.cg.shared.global [%0], [%1], 16;" :: "r"(dst), "l"(src) : "memory")
#define CP_COMMIT() asm volatile("cp.async.commit_group;" ::: "memory")
template<int N> __device__ __forceinline__ void cp_wait() {
    asm volatile("cp.async.wait_group %0;" :: "n"(N) : "memory");
}
// m16n8k16 fp16 mma, fp32 accum
__device__ __forceinline__ void mma_f16(float* c, const uint32_t* a, const uint32_t* b) {
    asm volatile(
        "mma.sync.aligned.m16n8k16.row.col.f32.f16.f16.f32 "
        "{%0,%1,%2,%3}, {%4,%5,%6,%7}, {%8,%9}, {%0,%1,%2,%3};"
        : "+f"(c[0]), "+f"(c[1]), "+f"(c[2]), "+f"(c[3])
        : "r"(a[0]), "r"(a[1]), "r"(a[2]), "r"(a[3]), "r"(b[0]), "r"(b[1]));
}
__device__ __forceinline__ void ldsm_x4(uint32_t* r, uint32_t addr) {
    asm volatile("ldmatrix.sync.aligned.m8n8.x4.shared.b16 {%0,%1,%2,%3}, [%4];"
        : "=r"(r[0]), "=r"(r[1]), "=r"(r[2]), "=r"(r[3]) : "r"(addr));
}
__device__ __forceinline__ uint32_t pack_h2(float lo, float hi) {
    __half2 h = __floats2half2_rn(lo, hi);
    return *reinterpret_cast<uint32_t*>(&h);
}
__device__ __forceinline__ __half2 u2h2(uint32_t u) {
    return *reinterpret_cast<__half2*>(&u);
}
__device__ __forceinline__ uint32_t h22u(__half2 h) {
    return *reinterpret_cast<uint32_t*>(&h);
}

// ============================================================
// Kernel 0: weight transpose + fp16 convert: W[K][N] -> Wt[N][K] (half)
// ============================================================
__global__ __launch_bounds__(256) void transpose_half_kernel(
    const float* __restrict__ W, __half* __restrict__ Wt, int K, int N)
{
    __shared__ float t[32][33];
    const int n0 = blockIdx.x * 32;
    const int k0 = blockIdx.y * 32;
    const int tx = threadIdx.x & 31;
    const int ty = threadIdx.x >> 5;
    #pragma unroll
    for (int r = 0; r < 4; r++)
        t[ty + r * 8][tx] = W[(size_t)(k0 + ty + r * 8) * N + n0 + tx];
    __syncthreads();
    #pragma unroll
    for (int r = 0; r < 4; r++)
        Wt[(size_t)(n0 + ty + r * 8) * K + k0 + tx] = __float2half_rn(t[tx][ty + r * 8]);
}

// ============================================================
// Kernel 1: LayerNorm + projections, 32 tokens per CTA (unchanged).
// ============================================================
#define LN_SMEM_BYTES (32 * 512 * 4)

__global__ __launch_bounds__(256) void ln_proj_kernel(
    const float* __restrict__ x,
    const float* __restrict__ Wv, const float* __restrict__ bv,
    const float* __restrict__ Wq, const float* __restrict__ bq,
    const float* __restrict__ Wk, const float* __restrict__ bk)
{
    extern __shared__ float smem[];
    float (*xn)[512] = (float(*)[512])smem;

    const int tb = blockIdx.x * 32;
    const int tid = threadIdx.x;
    const int lane = tid & 31, wid = tid >> 5;

    #pragma unroll
    for (int tt = 0; tt < 4; tt++) {
        const int t = wid * 4 + tt;
        const float* xin = x + (size_t)(tb + t) * E;
        float v[16];
        float s = 0.f, ss = 0.f;
        #pragma unroll
        for (int j = 0; j < 16; j++) {
            v[j] = xin[lane + j * 32];
            s += v[j];
            ss = fmaf(v[j], v[j], ss);
        }
        #pragma unroll
        for (int o = 16; o > 0; o >>= 1) {
            s  += __shfl_xor_sync(0xffffffffu, s, o);
            ss += __shfl_xor_sync(0xffffffffu, ss, o);
        }
        const float mean = s * (1.0f / E);
        const float var  = ss * (1.0f / E) - mean * mean;
        const float rstd = rsqrtf(var + 1e-5f);
        #pragma unroll
        for (int j = 0; j < 16; j++)
            xn[t][lane + j * 32] = (v[j] - mean) * rstd;
    }
    __syncthreads();

    const int bidx = tb >> 11;
    const int s0 = tb & (S - 1);

    #pragma unroll
    for (int rep = 0; rep < 2; rep++) {
        const int e = tid + rep * 256;
        const int h = e >> 6, d = e & 63;
        const float* w = Wv + (size_t)h * D * D + d;
        const float bvv = bv[e];
        float acc[32];
        #pragma unroll
        for (int t = 0; t < 32; t++) acc[t] = bvv;
        const float* xh = &xn[0][h * 64];
        #pragma unroll
        for (int i = 0; i < D; i += 4) {
            const float w0 = w[i * D];
            const float w1 = w[(i + 1) * D];
            const float w2 = w[(i + 2) * D];
            const float w3 = w[(i + 3) * D];
            #pragma unroll
            for (int t = 0; t < 32; t++) {
                const float4 xv = *(const float4*)&xh[t * 512 + i];
                float a0 = fmaf(xv.x, w0, acc[t]);
                float a1 = fmaf(xv.y, w1, a0);
                float a2 = fmaf(xv.z, w2, a1);
                acc[t] = fmaf(xv.w, w3, a2);
            }
        }
        uint32_t hb[16];
        #pragma unroll
        for (int t = 0; t < 16; t++) hb[t] = pack_h2(acc[t * 2], acc[t * 2 + 1]);
        uint4* dst = (uint4*)(g_Vt + ((size_t)(bidx * H + h) * D + d) * S + s0);
        const uint4* srcv = (const uint4*)hb;
        #pragma unroll
        for (int i = 0; i < 4; i++) dst[i] = srcv[i];
    }

    {
        const int t = tid >> 3, h = tid & 7;
        const float* wq = Wq + h * D;
        const float* wk = Wk + h * D;
        const float* xh = xn[t] + h * 64;
        float accq = bq[h], acck = bk[h];
        #pragma unroll
        for (int i = 0; i < D; i++) {
            const float xv = xh[i];
            accq = fmaf(xv, wq[i], accq);
            acck = fmaf(xv, wk[i], acck);
        }
        g_Q[((size_t)bidx * H + h) * S + s0 + t] = accq;
        g_K[((size_t)bidx * H + h) * S + s0 + t] = acck;
    }
}

// ============================================================
// Kernel 2: attention — R16 winner + triple-buffered V with
// cp.async wait_group 1 (prefetch depth 2), register-neutral.
// smem: KK 8KB | 3 x 8KB V buffers = 32KB
// ============================================================
#define ATT_SMEM_BYTES (8192 + 3 * 8192)

__global__ __launch_bounds__(128, 7) void attn_kernel()
{
    extern __shared__ float smem[];
    uint2* KK = (uint2*)smem;                // 1024 pairs
    const uint32_t sbase = smem_u32(smem);
    const uint32_t vtbuf = sbase + 8192;

    const int bh = blockIdx.y;
    const int q0 = blockIdx.x * 64;
    const int tid = threadIdx.x;
    const int lane = tid & 31, wid = tid >> 5;
    const int l7 = lane & 7;
    const int cl = lane & 3;

    const float CB = -0.1803368801111204f;   // -log2e/8
    const float CQ =  0.3606737602222409f;   // log2e/4
    for (int j = tid; j < S / 2; j += 128) {
        const float2 kv = *(const float2*)&g_K[(size_t)bh * S + 2 * j];
        uint2 e;
        e.x = pack_h2(kv.x, kv.y);
        e.y = pack_h2(kv.x * kv.x * CB, kv.y * kv.y * CB);
        KK[j] = e;
    }

    const int r0 = wid * 16 + (lane >> 2);   // 0..63
    const float qc0 = g_Q[(size_t)bh * S + q0 + r0] * CQ;
    const float qc1 = g_Q[(size_t)bh * S + q0 + r0 + 8] * CQ;
    const __half2 qc0h = __floats2half2_rn(qc0, qc0);
    const __half2 qc1h = __floats2half2_rn(qc1, qc1);

    const __half* Vg = g_Vt + (size_t)bh * D * S;   // [d][s]
    auto loadV = [&](int kc, int buf) {
        #pragma unroll
        for (int p = 0; p < 4; p++) {
            const int row = (tid >> 3) + p * 16;
            const int seg = tid & 7;
            const __half* src = Vg + (size_t)row * S + kc * 64 + seg * 8;
            const uint32_t dst = vtbuf + buf * 8192 +
                (uint32_t)(row * 128 + ((seg ^ (row & 7)) * 16));
            CP_ASYNC16(dst, src);
        }
    };

    uint32_t vRow[4];
    #pragma unroll
    for (int ntp = 0; ntp < 4; ntp++)
        vRow[ntp] = (uint32_t)((ntp * 16 + ((lane >> 4) & 1) * 8 + l7) * 128);
    const int selV = (lane >> 3) & 1;

    loadV(0, 0); CP_COMMIT();
    loadV(1, 1); CP_COMMIT();

    float acc[8][4];
    #pragma unroll
    for (int j = 0; j < 8; j++)
        #pragma unroll
        for (int l = 0; l < 4; l++) acc[j][l] = 0.f;
    float accd[4] = {0.f, 0.f, 0.f, 0.f};
    const uint32_t ones[2] = { 0x3C003C00u, 0x3C003C00u };

    const int NCH = S / 64;   // 32
    for (int kc = 0; kc < NCH; kc++) {
        // need load kc complete; load kc+1 may stay in flight
        if (kc + 1 < NCH) cp_wait<1>(); else cp_wait<0>();
        __syncthreads();
        // buf (kc+2)%3 was last read in chunk kc-1; all warps are past it
        if (kc + 2 < NCH) { loadV(kc + 2, (kc + 2) % 3); CP_COMMIT(); }

        const uint32_t vb = vtbuf + (uint32_t)((kc % 3) * 8192);
        #pragma unroll
        for (int ks = 0; ks < 4; ks++) {
            const int jb = kc * 32 + ks * 8;
            const uint2 e0 = KK[jb + cl];
            const uint2 e1 = KK[jb + cl + 4];
            uint32_t a[4];
            a[0] = h22u(h2exp2(__hfma2(qc0h, u2h2(e0.x), u2h2(e0.y))));
            a[1] = h22u(h2exp2(__hfma2(qc1h, u2h2(e0.x), u2h2(e0.y))));
            a[2] = h22u(h2exp2(__hfma2(qc0h, u2h2(e1.x), u2h2(e1.y))));
            a[3] = h22u(h2exp2(__hfma2(qc1h, u2h2(e1.x), u2h2(e1.y))));
            mma_f16(accd, a, ones);
            const uint32_t sw = (uint32_t)(((ks * 2 + selV) ^ l7) * 16);
            #pragma unroll
            for (int ntp = 0; ntp < 4; ntp++) {
                uint32_t bb[4];
                ldsm_x4(bb, vb + vRow[ntp] + sw);
                mma_f16(acc[ntp * 2],     a, bb);
                mma_f16(acc[ntp * 2 + 1], a, bb + 2);
            }
        }
    }

    const float inv0 = 1.0f / accd[0];
    const float inv1 = 1.0f / accd[2];

    const int b = bh >> 3, h = bh & 7;
    #pragma unroll
    for (int nt = 0; nt < 8; nt++) {
        const int col = nt * 8 + cl * 2;
        const size_t t0 = ((size_t)b * S + q0 + r0) * E + h * D + col;
        const size_t t1 = ((size_t)b * S + q0 + r0 + 8) * E + h * D + col;
        __half2 o0 = __floats2half2_rn(acc[nt][0] * inv0, acc[nt][1] * inv0);
        __half2 o1 = __floats2half2_rn(acc[nt][2] * inv1, acc[nt][3] * inv1);
        *(__half2*)&g_HO[t0] = o0;
        *(__half2*)&g_HO[t1] = o1;
    }
}

// ============================================================
// Kernel 3/4: fp16 mma GEMM — best-known config:
// 128x128 CTA tile, BK=64, 3-stage cp.async, 16B-XOR swizzle.
// ============================================================
#define GEMM_SMEM_BYTES (3 * 32768)

template<int MODE>
__global__ __launch_bounds__(256) void hgemm_kernel(
    const __half* __restrict__ Bt, const float* __restrict__ bias,
    const float* __restrict__ res, float* __restrict__ Cout,
    int N, int K)
{
    extern __shared__ float smem[];
    const __half* A = (MODE == 0) ? g_HO : g_MID;

    const int tid = threadIdx.x;
    const int lane = tid & 31, wid = tid >> 5;
    const int l7 = lane & 7;
    const int bm = blockIdx.y * 128;
    const int bn = blockIdx.x * 128;
    const int wm = wid >> 2;
    const int wn = wid & 3;
    const uint32_t sbase = smem_u32(smem);

    const int lr = tid >> 3;
    const int lg = tid & 7;

    auto load_tile = [&](int kc, int st) {
        #pragma unroll
        for (int p = 0; p < 4; p++) {
            const int r = lr + p * 32;
            const uint32_t dst = sbase + (uint32_t)(st * 32768 + r * 128 + ((lg ^ (r & 7)) * 16));
            CP_ASYNC16(dst, A + (size_t)(bm + r) * K + kc * 64 + lg * 8);
            CP_ASYNC16(dst + 16384u, Bt + (size_t)(bn + r) * K + kc * 64 + lg * 8);
        }
    };

    uint32_t aRow[4];
    #pragma unroll
    for (int mt = 0; mt < 4; mt++)
        aRow[mt] = (uint32_t)((wm * 64 + mt * 16 + ((lane >> 3) & 1) * 8 + l7) * 128);
    const int selA = (lane >> 4) & 1;
    uint32_t bRow[2];
    #pragma unroll
    for (int ntp = 0; ntp < 2; ntp++)
        bRow[ntp] = 16384u + (uint32_t)((wn * 32 + ntp * 16 + ((lane >> 4) & 1) * 8 + l7) * 128);
    const int selB = (lane >> 3) & 1;

    float acc[4][4][4];
    #pragma unroll
    for (int i = 0; i < 4; i++)
        #pragma unroll
        for (int j = 0; j < 4; j++)
            #pragma unroll
            for (int l = 0; l < 4; l++) acc[i][j][l] = 0.f;

    const int nc = K / 64;
    load_tile(0, 0); CP_COMMIT();
    load_tile(1, 1); CP_COMMIT();

    for (int kc = 0; kc < nc; kc++) {
        const int st = kc % 3;
        if (kc + 1 < nc) cp_wait<1>(); else cp_wait<0>();
        __syncthreads();
        if (kc + 2 < nc) { load_tile(kc + 2, (kc + 2) % 3); CP_COMMIT(); }

        const uint32_t stb = sbase + (uint32_t)(st * 32768);
        #pragma unroll
        for (int ks = 0; ks < 4; ks++) {
            const uint32_t swA = (uint32_t)(((ks * 2 + selA) ^ l7) * 16);
            const uint32_t swB = (uint32_t)(((ks * 2 + selB) ^ l7) * 16);
            uint32_t a[4][4], b01[4], b23[4];
            #pragma unroll
            for (int mt = 0; mt < 4; mt++) ldsm_x4(a[mt], stb + aRow[mt] + swA);
            ldsm_x4(b01, stb + bRow[0] + swB);
            ldsm_x4(b23, stb + bRow[1] + swB);
            #pragma unroll
            for (int mt = 0; mt < 4; mt++) {
                mma_f16(acc[mt][0], a[mt], b01);
                mma_f16(acc[mt][1], a[mt], b01 + 2);
                mma_f16(acc[mt][2], a[mt], b23);
                mma_f16(acc[mt][3], a[mt], b23 + 2);
            }
        }
    }

    #pragma unroll
    for (int mt = 0; mt < 4; mt++) {
        const int r0 = bm + wm * 64 + mt * 16 + (lane >> 2);
        #pragma unroll
        for (int nt = 0; nt < 4; nt++) {
            const int col = bn + wn * 32 + nt * 8 + (lane & 3) * 2;
            const float bz0 = bias[col], bz1 = bias[col + 1];
            float c0 = acc[mt][nt][0] + bz0;
            float c1 = acc[mt][nt][1] + bz1;
            float c2 = acc[mt][nt][2] + bz0;
            float c3 = acc[mt][nt][3] + bz1;
            const size_t g0 = (size_t)r0 * N + col;
            const size_t g1 = (size_t)(r0 + 8) * N + col;
            if (MODE == 0) {
                c0 = c0 * normcdff(c0);
                c1 = c1 * normcdff(c1);
                c2 = c2 * normcdff(c2);
                c3 = c3 * normcdff(c3);
                *(__half2*)&g_MID[g0] = __floats2half2_rn(c0, c1);
                *(__half2*)&g_MID[g1] = __floats2half2_rn(c2, c3);
            } else {
                const float2 ra = *(const float2*)&res[g0];
                const float2 rb = *(const float2*)&res[g1];
                float2 v0; v0.x = c0 + ra.x; v0.y = c1 + ra.y;
                float2 v1; v1.x = c2 + rb.x; v1.y = c3 + rb.y;
                *(float2*)&Cout[g0] = v0;
                *(float2*)&Cout[g1] = v1;
            }
        }
    }
}

// ============================================================
extern "C" void kernel_launch(void* const* d_in, const int* in_sizes, int n_in,
                              void* d_out, int out_size)
{
    const float* input1 = (const float*)d_in[0];
    const float* Wv = (const float*)d_in[1];
    const float* bv = (const float*)d_in[2];
    const float* Wq = (const float*)d_in[3];
    const float* bq = (const float*)d_in[4];
    const float* Wk = (const float*)d_in[5];
    const float* bk = (const float*)d_in[6];
    const float* W1 = (const float*)d_in[7];
    const float* b1 = (const float*)d_in[8];
    const float* W2 = (const float*)d_in[9];
    const float* b2 = (const float*)d_in[10];
    float* out = (float*)d_out;

    __half* s_Wt1; cudaGetSymbolAddress((void**)&s_Wt1, g_Wt1);
    __half* s_Wt2; cudaGetSymbolAddress((void**)&s_Wt2, g_Wt2);

    static bool s_init = false;
    if (!s_init) {
        cudaFuncSetAttribute(ln_proj_kernel, cudaFuncAttributeMaxDynamicSharedMemorySize, LN_SMEM_BYTES);
        cudaFuncSetAttribute(attn_kernel, cudaFuncAttributeMaxDynamicSharedMemorySize, ATT_SMEM_BYTES);
        cudaFuncSetAttribute(hgemm_kernel<0>, cudaFuncAttributeMaxDynamicSharedMemorySize, GEMM_SMEM_BYTES);
        cudaFuncSetAttribute(hgemm_kernel<1>, cudaFuncAttributeMaxDynamicSharedMemorySize, GEMM_SMEM_BYTES);
        s_init = true;
    }

    transpose_half_kernel<<<dim3(FF / 32, E / 32), 256>>>(W1, s_Wt1, E, FF);
    transpose_half_kernel<<<dim3(E / 32, FF / 32), 256>>>(W2, s_Wt2, FF, E);

    ln_proj_kernel<<<NTOK / 32, 256, LN_SMEM_BYTES>>>(input1, Wv, bv, Wq, bq, Wk, bk);
    attn_kernel<<<dim3(S / 64, B * H), 128, ATT_SMEM_BYTES>>>();

    hgemm_kernel<0><<<dim3(FF / 128, NTOK / 128), 256, GEMM_SMEM_BYTES>>>(s_Wt1, b1, nullptr, nullptr, FF, E);
    hgemm_kernel<1><<<dim3(E / 128, NTOK / 128), 256, GEMM_SMEM_BYTES>>>(s_Wt2, b2, input1, out, E, FF);
}